// round 8
// baseline (speedup 1.0000x reference)
#include <cuda_runtime.h>
#include <math.h>
#include <stdint.h>

// Problem constants (B=4, T=2048, D=1024, FF=4096, E=8, K=2)
#define N_TOK   8192
#define NE      8
#define D_MODEL 1024
#define FF_DIM  4096
#define NK      16384            // N_TOK * 2 expanded rows
#define CHUNK   2048             // NK / NE rows per expert chunk

// Scratch (__device__ globals: allocation-guard-safe)
__device__ uint32_t g_w1t[(size_t)NE * D_MODEL * FF_DIM];  // 134 MB tf32 w1
__device__ uint32_t g_w2t[(size_t)NE * FF_DIM * D_MODEL];  // 134 MB tf32 w2
__device__ uint32_t g_xt[(size_t)N_TOK * D_MODEL];         // 33.5 MB tf32 x
__device__ uint32_t g_h[(size_t)NK * FF_DIM];              // 268 MB tf32 h
__device__ float    g_y[(size_t)NK * D_MODEL];             // 64 MB outputs
__device__ int      g_expert[NK];
__device__ float    g_wflat[NK];
__device__ int      g_rev[NK];
__device__ float    g_sw[NK];
__device__ int      g_pos[NK];                             // inverse perm

// ---------------------------------------------------------------------------
// fp32 -> tf32 round-to-nearest (bias-free; mandatory for accuracy)
__device__ __forceinline__ uint32_t f2tf(float f) {
    uint32_t r;
    asm("cvt.rna.tf32.f32 %0, %1;" : "=r"(r) : "f"(f));
    return r;
}

// m16n8k8 tf32 HMMA (baseline PTX, works on compute_103)
__device__ __forceinline__ void mma16n8k8(float* d, const uint32_t* a,
                                          const uint32_t* b) {
    asm volatile(
        "mma.sync.aligned.m16n8k8.row.col.f32.tf32.tf32.f32 "
        "{%0,%1,%2,%3}, {%4,%5,%6,%7}, {%8,%9}, {%0,%1,%2,%3};"
        : "+f"(d[0]), "+f"(d[1]), "+f"(d[2]), "+f"(d[3])
        : "r"(a[0]), "r"(a[1]), "r"(a[2]), "r"(a[3]), "r"(b[0]), "r"(b[1]));
}

// cp.async (sm_80 baseline)
__device__ __forceinline__ void cp16(uint32_t dst, const void* src) {
    asm volatile("cp.async.cg.shared.global [%0], [%1], 16;"
                 :: "r"(dst), "l"(src));
}
#define CP_COMMIT() asm volatile("cp.async.commit_group;" ::: "memory")
#define CP_WAIT(n)  asm volatile("cp.async.wait_group %0;" :: "n"(n) : "memory")

__device__ __forceinline__ float gelu_exact(float v) {
    return 0.5f * v * (1.f + erff(v * 0.70710678118654752f));
}

// ---------------------------------------------------------------------------
// tf32 pre-conversion: streaming float4 -> uint4 (RN)
// ---------------------------------------------------------------------------
__global__ void conv_tf32_kernel(const float4* __restrict__ src,
                                 uint4* __restrict__ dst, int n4) {
    for (int i = blockIdx.x * blockDim.x + threadIdx.x; i < n4;
         i += gridDim.x * blockDim.x) {
        float4 v = src[i];
        uint4 o;
        o.x = f2tf(v.x); o.y = f2tf(v.y); o.z = f2tf(v.z); o.w = f2tf(v.w);
        dst[i] = o;
    }
}

// ---------------------------------------------------------------------------
// Router (fp32, exact): logits, top-2, softmax-of-2. One warp per token.
// ---------------------------------------------------------------------------
__global__ void router_kernel(const float* __restrict__ x,
                              const float* __restrict__ rw) {
    int gwarp = (blockIdx.x * blockDim.x + threadIdx.x) >> 5;
    int lane  = threadIdx.x & 31;
    if (gwarp >= N_TOK) return;
    const float* xr = x + (size_t)gwarp * D_MODEL;
    float acc[NE];
#pragma unroll
    for (int e = 0; e < NE; e++) acc[e] = 0.f;
    for (int c = lane; c < D_MODEL; c += 32) {
        float xv = xr[c];
#pragma unroll
        for (int e = 0; e < NE; e++) acc[e] += xv * rw[e * D_MODEL + c];
    }
#pragma unroll
    for (int e = 0; e < NE; e++)
#pragma unroll
        for (int o = 16; o > 0; o >>= 1)
            acc[e] += __shfl_xor_sync(0xffffffffu, acc[e], o);
    if (lane == 0) {
        int i0 = 0; float v0 = acc[0];
#pragma unroll
        for (int e = 1; e < NE; e++) if (acc[e] > v0) { v0 = acc[e]; i0 = e; }
        int i1 = -1; float v1 = -INFINITY;
#pragma unroll
        for (int e = 0; e < NE; e++)
            if (e != i0 && acc[e] > v1) { v1 = acc[e]; i1 = e; }
        float ex = expf(v1 - v0);
        float inv = 1.f / (1.f + ex);
        g_expert[gwarp * 2 + 0] = i0;
        g_expert[gwarp * 2 + 1] = i1;
        g_wflat[gwarp * 2 + 0] = inv;
        g_wflat[gwarp * 2 + 1] = ex * inv;
    }
}

// ---------------------------------------------------------------------------
// Stable counting sort by expert id; also emits inverse permutation g_pos.
// ---------------------------------------------------------------------------
__global__ void sort_kernel() {
    __shared__ int cnt[256][NE];
    __shared__ int base[NE];
    int tid = threadIdx.x;
    int start = tid * 64;
    int my[NE];
#pragma unroll
    for (int e = 0; e < NE; e++) my[e] = 0;
    for (int j = 0; j < 64; j++) my[g_expert[start + j]]++;
#pragma unroll
    for (int e = 0; e < NE; e++) cnt[tid][e] = my[e];
    __syncthreads();
    if (tid < NE) {
        int e = tid, run = 0;
        for (int t = 0; t < 256; t++) { int c = cnt[t][e]; cnt[t][e] = run; run += c; }
        base[e] = run;
    }
    __syncthreads();
    if (tid == 0) {
        int run = 0;
        for (int e = 0; e < NE; e++) { int c = base[e]; base[e] = run; run += c; }
    }
    __syncthreads();
    int off[NE];
#pragma unroll
    for (int e = 0; e < NE; e++) off[e] = base[e] + cnt[tid][e];
    for (int j = 0; j < 64; j++) {
        int i = start + j;
        int e = g_expert[i];
        int pos = off[e]++;
        g_rev[pos] = i >> 1;
        g_sw[pos]  = g_wflat[i];
        g_pos[i]   = pos;
    }
}

// ---------------------------------------------------------------------------
// tf32 mma.sync GEMMs, 3-stage cp.async ring, one __syncthreads per stage.
// BM=BN=128, BK=32, 256 threads (8 warps, 4x2), warp tile 32x64.
// Smem holds PRE-CONVERTED tf32 bits; inner loop is pure LDS + MMA.
// Pitches: A 36, B 136 u32 (conflict-free fragment LDS).
// ---------------------------------------------------------------------------
#define BM 128
#define BN 128
#define BKF 32
#define PA 36
#define PB 136
#define STAGES 3
#define A_BUF (BM * PA)                  // 4608 u32
#define B_BUF (BKF * PB)                 // 4352 u32
#define SMEM_U32 (STAGES * (A_BUF + B_BUF) + 128)
#define SMEM_BYTES (SMEM_U32 * 4)        // 108,032 B

template <bool GATHER>
__device__ __forceinline__ void issue_stage(
    uint32_t sA, uint32_t sB, const uint32_t* __restrict__ Abase,
    const int* __restrict__ srev, size_t lda,
    const uint32_t* __restrict__ Bsrc, size_t ldb, int tid) {
#pragma unroll
    for (int j = 0; j < 4; j++) {
        int idx = tid + j * 256;               // 0..1023
        int row = idx >> 3, c4 = (idx & 7) << 2;
        const uint32_t* src = GATHER
            ? Abase + (size_t)srev[row] * lda + c4
            : Abase + (size_t)row * lda + c4;
        cp16(sA + (uint32_t)(row * PA + c4) * 4, src);
    }
#pragma unroll
    for (int j = 0; j < 4; j++) {
        int idx = tid + j * 256;
        int k = idx >> 5, c4 = (idx & 31) << 2;
        cp16(sB + (uint32_t)(k * PB + c4) * 4, Bsrc + (size_t)k * ldb + c4);
    }
}

// Pure LDS + MMA on one smem stage: 4 k8 steps, 16 HMMA each.
__device__ __forceinline__ void compute_stage(
    const uint32_t* __restrict__ As, const uint32_t* __restrict__ Bs,
    int lane, int wm, int wn, float acc[2][8][4]) {
#pragma unroll
    for (int k8 = 0; k8 < 4; k8++) {
        uint32_t a[2][4];
#pragma unroll
        for (int m2 = 0; m2 < 2; m2++) {
            int rb = wm * 32 + m2 * 16 + (lane >> 2);
            int c = k8 * 8 + (lane & 3);
            a[m2][0] = As[rb * PA + c];
            a[m2][1] = As[(rb + 8) * PA + c];
            a[m2][2] = As[rb * PA + c + 4];
            a[m2][3] = As[(rb + 8) * PA + c + 4];
        }
        uint32_t b[8][2];
#pragma unroll
        for (int n2 = 0; n2 < 8; n2++) {
            int n = wn * 64 + n2 * 8 + (lane >> 2);
            int k = k8 * 8 + (lane & 3);
            b[n2][0] = Bs[k * PB + n];
            b[n2][1] = Bs[(k + 4) * PB + n];
        }
#pragma unroll
        for (int m2 = 0; m2 < 2; m2++)
#pragma unroll
            for (int n2 = 0; n2 < 8; n2++)
                mma16n8k8(acc[m2][n2], a[m2], b[n2]);
    }
}

// Shared multistage mainloop
template <bool GATHER>
__device__ __forceinline__ void gemm_mainloop(
    const uint32_t* __restrict__ Abase, const int* __restrict__ srev,
    size_t lda, const uint32_t* __restrict__ Bsrc, size_t ldb,
    uint32_t* As0, uint32_t* Bs0, uint32_t sA, uint32_t sB,
    int S, int tid, int lane, int wm, int wn, float acc[2][8][4]) {
#pragma unroll
    for (int p = 0; p < STAGES - 1; p++) {
        issue_stage<GATHER>(sA + p * A_BUF * 4, sB + p * B_BUF * 4,
                            Abase + p * BKF, srev, lda,
                            Bsrc + (size_t)(p * BKF) * ldb, ldb, tid);
        CP_COMMIT();
    }
    for (int s = 0; s < S; s++) {
        if (s + 1 < S) CP_WAIT(1); else CP_WAIT(0);
        __syncthreads();
        int nx = s + STAGES - 1;
        if (nx < S) {
            int bufn = nx % STAGES;
            issue_stage<GATHER>(sA + bufn * A_BUF * 4, sB + bufn * B_BUF * 4,
                                Abase + nx * BKF, srev, lda,
                                Bsrc + (size_t)(nx * BKF) * ldb, ldb, tid);
            CP_COMMIT();
        }
        int buf = s % STAGES;
        compute_stage(As0 + buf * A_BUF, Bs0 + buf * B_BUF, lane, wm, wn, acc);
    }
}

// GEMM1: h = tf32( gelu( gather(xt, rev) @ w1t[e] ) )   [K=1024, 32 stages]
__global__ __launch_bounds__(256, 2) void gemm1_mma() {
    extern __shared__ uint32_t smem[];
    uint32_t* As0 = smem;
    uint32_t* Bs0 = smem + STAGES * A_BUF;
    int* srev = (int*)(smem + STAGES * (A_BUF + B_BUF));
    uint32_t sbase = (uint32_t)__cvta_generic_to_shared(smem);
    uint32_t sA = sbase, sB = sbase + STAGES * A_BUF * 4;

    int tid = threadIdx.x, lane = tid & 31, wid = tid >> 5;
    int mt = blockIdx.x, ntb = blockIdx.y, e = blockIdx.z;
    const uint32_t* w1e = g_w1t + (size_t)e * D_MODEL * FF_DIM;
    int nb = ntb * BN;
    if (tid < BM) srev[tid] = g_rev[e * CHUNK + mt * BM + tid];
    __syncthreads();

    int wm = wid & 3, wn = wid >> 2;
    float acc[2][8][4];
#pragma unroll
    for (int i = 0; i < 2; i++)
#pragma unroll
        for (int j = 0; j < 8; j++)
#pragma unroll
            for (int c = 0; c < 4; c++) acc[i][j][c] = 0.f;

    gemm_mainloop<true>(g_xt, srev, D_MODEL, w1e + nb, FF_DIM,
                        As0, Bs0, sA, sB, D_MODEL / BKF,
                        tid, lane, wm, wn, acc);

    // Epilogue: GELU + tf32 round -> g_h (u32)
    int hrow0 = e * CHUNK + mt * BM;
#pragma unroll
    for (int m2 = 0; m2 < 2; m2++) {
        int r0 = wm * 32 + m2 * 16 + (lane >> 2);
#pragma unroll
        for (int half = 0; half < 2; half++) {
            uint32_t* hr =
                g_h + (size_t)(hrow0 + r0 + half * 8) * FF_DIM + nb;
#pragma unroll
            for (int n2 = 0; n2 < 8; n2++) {
                int col = wn * 64 + n2 * 8 + 2 * (lane & 3);
                uint2 o;
                o.x = f2tf(gelu_exact(acc[m2][n2][half * 2 + 0]));
                o.y = f2tf(gelu_exact(acc[m2][n2][half * 2 + 1]));
                *(uint2*)(hr + col) = o;
            }
        }
    }
}

// GEMM2: y = (h @ w2t[e]) * sw   [K=4096, 128 stages]
__global__ __launch_bounds__(256, 2) void gemm2_mma() {
    extern __shared__ uint32_t smem[];
    uint32_t* As0 = smem;
    uint32_t* Bs0 = smem + STAGES * A_BUF;
    uint32_t sbase = (uint32_t)__cvta_generic_to_shared(smem);
    uint32_t sA = sbase, sB = sbase + STAGES * A_BUF * 4;

    int tid = threadIdx.x, lane = tid & 31, wid = tid >> 5;
    int mt = blockIdx.x, ntb = blockIdx.y, e = blockIdx.z;
    const uint32_t* w2e = g_w2t + (size_t)e * FF_DIM * D_MODEL;
    const uint32_t* Aep = g_h + (size_t)(e * CHUNK + mt * BM) * FF_DIM;
    int nb = ntb * BN;

    int wm = wid & 3, wn = wid >> 2;
    float acc[2][8][4];
#pragma unroll
    for (int i = 0; i < 2; i++)
#pragma unroll
        for (int j = 0; j < 8; j++)
#pragma unroll
            for (int c = 0; c < 4; c++) acc[i][j][c] = 0.f;

    gemm_mainloop<false>(Aep, nullptr, FF_DIM, w2e + nb, D_MODEL,
                         As0, Bs0, sA, sB, FF_DIM / BKF,
                         tid, lane, wm, wn, acc);

    // Epilogue: gate-weight scale -> g_y (sorted order)
    int srow0 = e * CHUNK + mt * BM;
#pragma unroll
    for (int m2 = 0; m2 < 2; m2++) {
        int r0 = wm * 32 + m2 * 16 + (lane >> 2);
#pragma unroll
        for (int half = 0; half < 2; half++) {
            int srow = srow0 + r0 + half * 8;
            float w = g_sw[srow];
            float* yr = g_y + (size_t)srow * D_MODEL + nb;
#pragma unroll
            for (int n2 = 0; n2 < 8; n2++) {
                int col = wn * 64 + n2 * 8 + 2 * (lane & 3);
                float2 o;
                o.x = acc[m2][n2][half * 2 + 0] * w;
                o.y = acc[m2][n2][half * 2 + 1] * w;
                *(float2*)(yr + col) = o;
            }
        }
    }
}

// Combine: out[t] = y[pos(t,0)] + y[pos(t,1)]  (full overwrite, no atomics)
__global__ void combine_kernel(float* __restrict__ out) {
    int t = blockIdx.x;
    int c = threadIdx.x * 4;
    int p0 = g_pos[2 * t], p1 = g_pos[2 * t + 1];
    float4 a = *(const float4*)(g_y + (size_t)p0 * D_MODEL + c);
    float4 b = *(const float4*)(g_y + (size_t)p1 * D_MODEL + c);
    float4 o;
    o.x = a.x + b.x; o.y = a.y + b.y; o.z = a.z + b.z; o.w = a.w + b.w;
    *(float4*)(out + (size_t)t * D_MODEL + c) = o;
}

// ---------------------------------------------------------------------------
extern "C" void kernel_launch(void* const* d_in, const int* in_sizes, int n_in,
                              void* d_out, int out_size) {
    const float* x  = (const float*)d_in[0];   // [4,2048,1024]
    const float* rw = (const float*)d_in[1];   // [8,1024]
    const float* w1 = (const float*)d_in[2];   // [8,1024,4096]
    const float* w2 = (const float*)d_in[3];   // [8,4096,1024]
    float* out = (float*)d_out;                // [4,2048,1024]

    // Idempotent, called every time (no static guards per harness rules)
    cudaFuncSetAttribute(gemm1_mma,
        cudaFuncAttributeMaxDynamicSharedMemorySize, SMEM_BYTES);
    cudaFuncSetAttribute(gemm2_mma,
        cudaFuncAttributeMaxDynamicSharedMemorySize, SMEM_BYTES);

    uint32_t *w1t_p, *w2t_p, *xt_p;
    cudaGetSymbolAddress((void**)&w1t_p, g_w1t);
    cudaGetSymbolAddress((void**)&w2t_p, g_w2t);
    cudaGetSymbolAddress((void**)&xt_p, g_xt);

    // Pre-convert weights + activations to tf32 (RN)
    int nw = NE * D_MODEL * FF_DIM / 4;        // 8.39M float4 each
    conv_tf32_kernel<<<4096, 256>>>((const float4*)w1, (uint4*)w1t_p, nw);
    conv_tf32_kernel<<<4096, 256>>>((const float4*)w2, (uint4*)w2t_p, nw);
    conv_tf32_kernel<<<2048, 256>>>((const float4*)x, (uint4*)xt_p,
                                    N_TOK * D_MODEL / 4);

    router_kernel<<<N_TOK / 8, 256>>>(x, rw);
    sort_kernel<<<1, 256>>>();

    dim3 g1(CHUNK / BM, FF_DIM / BN, NE);      // 16 x 32 x 8
    gemm1_mma<<<g1, 256, SMEM_BYTES>>>();
    dim3 g2(CHUNK / BM, D_MODEL / BN, NE);     // 16 x 8 x 8
    gemm2_mma<<<g2, 256, SMEM_BYTES>>>();

    combine_kernel<<<N_TOK, 256>>>(out);
}

// round 9
// speedup vs baseline: 1.0674x; 1.0674x over previous
#include <cuda_runtime.h>
#include <math.h>
#include <stdint.h>

// Problem constants (B=4, T=2048, D=1024, FF=4096, E=8, K=2)
#define N_TOK   8192
#define NE      8
#define D_MODEL 1024
#define FF_DIM  4096
#define NK      16384            // N_TOK * 2 expanded rows
#define CHUNK   2048             // NK / NE rows per expert chunk

// Scratch (__device__ globals: allocation-guard-safe)
__device__ uint32_t g_w1t[(size_t)NE * D_MODEL * FF_DIM];  // 134 MB tf32 w1
__device__ uint32_t g_w2t[(size_t)NE * FF_DIM * D_MODEL];  // 134 MB tf32 w2
__device__ uint32_t g_xt[(size_t)N_TOK * D_MODEL];         // 33.5 MB tf32 x
__device__ uint32_t g_h[(size_t)NK * FF_DIM];              // 268 MB tf32 h
__device__ float    g_y[(size_t)NK * D_MODEL];             // 64 MB outputs
__device__ int      g_expert[NK];
__device__ float    g_wflat[NK];
__device__ int      g_rev[NK];
__device__ float    g_sw[NK];
__device__ int      g_pos[NK];                             // inverse perm

// ---------------------------------------------------------------------------
__device__ __forceinline__ uint32_t f2tf(float f) {        // fp32->tf32 RN
    uint32_t r;
    asm("cvt.rna.tf32.f32 %0, %1;" : "=r"(r) : "f"(f));
    return r;
}

// m16n8k8 tf32 HMMA (baseline PTX, works on compute_103)
__device__ __forceinline__ void mma16n8k8(float* d, const uint32_t* a,
                                          const uint32_t* b) {
    asm volatile(
        "mma.sync.aligned.m16n8k8.row.col.f32.tf32.tf32.f32 "
        "{%0,%1,%2,%3}, {%4,%5,%6,%7}, {%8,%9}, {%0,%1,%2,%3};"
        : "+f"(d[0]), "+f"(d[1]), "+f"(d[2]), "+f"(d[3])
        : "r"(a[0]), "r"(a[1]), "r"(a[2]), "r"(a[3]), "r"(b[0]), "r"(b[1]));
}

// ldmatrix x4: four 8x8-b16 tiles == four 8x4-u32 tiles (tf32 A fragments)
__device__ __forceinline__ void ldsm_x4(uint32_t* r, uint32_t addr) {
    asm volatile(
        "ldmatrix.sync.aligned.m8n8.x4.shared.b16 {%0,%1,%2,%3}, [%4];"
        : "=r"(r[0]), "=r"(r[1]), "=r"(r[2]), "=r"(r[3]) : "r"(addr));
}

// cp.async (sm_80 baseline)
__device__ __forceinline__ void cp16(uint32_t dst, const void* src) {
    asm volatile("cp.async.cg.shared.global [%0], [%1], 16;"
                 :: "r"(dst), "l"(src));
}
#define CP_COMMIT() asm volatile("cp.async.commit_group;" ::: "memory")
#define CP_WAIT(n)  asm volatile("cp.async.wait_group %0;" :: "n"(n) : "memory")

__device__ __forceinline__ float gelu_exact(float v) {
    return 0.5f * v * (1.f + erff(v * 0.70710678118654752f));
}

// ---------------------------------------------------------------------------
// tf32 pre-conversion: streaming float4 -> uint4 (RN)
__global__ void conv_tf32_kernel(const float4* __restrict__ src,
                                 uint4* __restrict__ dst, int n4) {
    for (int i = blockIdx.x * blockDim.x + threadIdx.x; i < n4;
         i += gridDim.x * blockDim.x) {
        float4 v = src[i];
        uint4 o;
        o.x = f2tf(v.x); o.y = f2tf(v.y); o.z = f2tf(v.z); o.w = f2tf(v.w);
        dst[i] = o;
    }
}

// ---------------------------------------------------------------------------
// Router (fp32, exact): logits, top-2, softmax-of-2. One warp per token.
// ---------------------------------------------------------------------------
__global__ void router_kernel(const float* __restrict__ x,
                              const float* __restrict__ rw) {
    int gwarp = (blockIdx.x * blockDim.x + threadIdx.x) >> 5;
    int lane  = threadIdx.x & 31;
    if (gwarp >= N_TOK) return;
    const float* xr = x + (size_t)gwarp * D_MODEL;
    float acc[NE];
#pragma unroll
    for (int e = 0; e < NE; e++) acc[e] = 0.f;
    for (int c = lane; c < D_MODEL; c += 32) {
        float xv = xr[c];
#pragma unroll
        for (int e = 0; e < NE; e++) acc[e] += xv * rw[e * D_MODEL + c];
    }
#pragma unroll
    for (int e = 0; e < NE; e++)
#pragma unroll
        for (int o = 16; o > 0; o >>= 1)
            acc[e] += __shfl_xor_sync(0xffffffffu, acc[e], o);
    if (lane == 0) {
        int i0 = 0; float v0 = acc[0];
#pragma unroll
        for (int e = 1; e < NE; e++) if (acc[e] > v0) { v0 = acc[e]; i0 = e; }
        int i1 = -1; float v1 = -INFINITY;
#pragma unroll
        for (int e = 0; e < NE; e++)
            if (e != i0 && acc[e] > v1) { v1 = acc[e]; i1 = e; }
        float ex = expf(v1 - v0);
        float inv = 1.f / (1.f + ex);
        g_expert[gwarp * 2 + 0] = i0;
        g_expert[gwarp * 2 + 1] = i1;
        g_wflat[gwarp * 2 + 0] = inv;
        g_wflat[gwarp * 2 + 1] = ex * inv;
    }
}

// ---------------------------------------------------------------------------
// Stable counting sort by expert id; also emits inverse permutation g_pos.
// ---------------------------------------------------------------------------
__global__ void sort_kernel() {
    __shared__ int cnt[256][NE];
    __shared__ int base[NE];
    int tid = threadIdx.x;
    int start = tid * 64;
    int my[NE];
#pragma unroll
    for (int e = 0; e < NE; e++) my[e] = 0;
    for (int j = 0; j < 64; j++) my[g_expert[start + j]]++;
#pragma unroll
    for (int e = 0; e < NE; e++) cnt[tid][e] = my[e];
    __syncthreads();
    if (tid < NE) {
        int e = tid, run = 0;
        for (int t = 0; t < 256; t++) { int c = cnt[t][e]; cnt[t][e] = run; run += c; }
        base[e] = run;
    }
    __syncthreads();
    if (tid == 0) {
        int run = 0;
        for (int e = 0; e < NE; e++) { int c = base[e]; base[e] = run; run += c; }
    }
    __syncthreads();
    int off[NE];
#pragma unroll
    for (int e = 0; e < NE; e++) off[e] = base[e] + cnt[tid][e];
    for (int j = 0; j < 64; j++) {
        int i = start + j;
        int e = g_expert[i];
        int pos = off[e]++;
        g_rev[pos] = i >> 1;
        g_sw[pos]  = g_wflat[i];
        g_pos[i]   = pos;
    }
}

// ---------------------------------------------------------------------------
// tf32 mma.sync GEMMs, 3-stage cp.async ring, 128 threads (4 warps, 2x2),
// warp tile 64x64 (4 m-frags x 8 n-frags). A frags via ldmatrix.x4.
// Smem: pre-converted tf32; pitches A 36 / B 136 u32 (conflict-free).
// ---------------------------------------------------------------------------
#define BM 128
#define BN 128
#define BKF 32
#define PA 36
#define PB 136
#define STAGES 3
#define NTHREADS 128
#define A_BUF (BM * PA)                  // 4608 u32
#define B_BUF (BKF * PB)                 // 4352 u32
#define SMEM_U32 (STAGES * (A_BUF + B_BUF) + 128)
#define SMEM_BYTES (SMEM_U32 * 4)        // 108,032 B

template <bool GATHER>
__device__ __forceinline__ void issue_stage(
    uint32_t sA, uint32_t sB, const uint32_t* __restrict__ Abase,
    const int* __restrict__ srev, size_t lda,
    const uint32_t* __restrict__ Bsrc, size_t ldb, int tid) {
#pragma unroll
    for (int j = 0; j < 8; j++) {        // A: 128 rows x 8 float4
        int idx = tid + j * NTHREADS;    // 0..1023
        int row = idx >> 3, c4 = (idx & 7) << 2;
        const uint32_t* src = GATHER
            ? Abase + (size_t)srev[row] * lda + c4
            : Abase + (size_t)row * lda + c4;
        cp16(sA + (uint32_t)(row * PA + c4) * 4, src);
    }
#pragma unroll
    for (int j = 0; j < 8; j++) {        // B: 32 k-rows x 32 float4
        int idx = tid + j * NTHREADS;
        int k = idx >> 5, c4 = (idx & 31) << 2;
        cp16(sB + (uint32_t)(k * PB + c4) * 4, Bsrc + (size_t)k * ldb + c4);
    }
}

// One smem stage: 4 k8 steps x (4 ldsm.x4 + 16 LDS + 32 HMMA)
__device__ __forceinline__ void compute_stage(
    uint32_t aAddr, const uint32_t* __restrict__ Bs,
    int lane, int wm, int wn, float acc[4][8][4]) {
    // ldmatrix lane->tile-row mapping (4 tiles: m0k0, m8k0, m0k4, m8k4)
    int g = lane >> 3, tr = lane & 7;
    uint32_t lbase = aAddr +
        (uint32_t)(((wm * 64 + (g & 1) * 8 + tr) * PA + (g >> 1) * 4) * 4);
#pragma unroll
    for (int k8 = 0; k8 < 4; k8++) {
        uint32_t a[4][4];
#pragma unroll
        for (int m2 = 0; m2 < 4; m2++)
            ldsm_x4(a[m2], lbase + (uint32_t)((m2 * 16 * PA + k8 * 8) * 4));
        uint32_t b[8][2];
#pragma unroll
        for (int n2 = 0; n2 < 8; n2++) {
            int n = wn * 64 + n2 * 8 + (lane >> 2);
            int k = k8 * 8 + (lane & 3);
            b[n2][0] = Bs[k * PB + n];
            b[n2][1] = Bs[(k + 4) * PB + n];
        }
#pragma unroll
        for (int m2 = 0; m2 < 4; m2++)
#pragma unroll
            for (int n2 = 0; n2 < 8; n2++)
                mma16n8k8(acc[m2][n2], a[m2], b[n2]);
    }
}

template <bool GATHER>
__device__ __forceinline__ void gemm_mainloop(
    const uint32_t* __restrict__ Abase, const int* __restrict__ srev,
    size_t lda, const uint32_t* __restrict__ Bsrc, size_t ldb,
    uint32_t* Bs0, uint32_t sA, uint32_t sB,
    int S, int tid, int lane, int wm, int wn, float acc[4][8][4]) {
#pragma unroll
    for (int p = 0; p < STAGES - 1; p++) {
        issue_stage<GATHER>(sA + p * A_BUF * 4, sB + p * B_BUF * 4,
                            Abase + p * BKF, srev, lda,
                            Bsrc + (size_t)(p * BKF) * ldb, ldb, tid);
        CP_COMMIT();
    }
    for (int s = 0; s < S; s++) {
        if (s + 1 < S) CP_WAIT(1); else CP_WAIT(0);
        __syncthreads();
        int nx = s + STAGES - 1;
        if (nx < S) {
            int bufn = nx % STAGES;
            issue_stage<GATHER>(sA + bufn * A_BUF * 4, sB + bufn * B_BUF * 4,
                                Abase + nx * BKF, srev, lda,
                                Bsrc + (size_t)(nx * BKF) * ldb, ldb, tid);
            CP_COMMIT();
        }
        int buf = s % STAGES;
        compute_stage(sA + buf * A_BUF * 4, Bs0 + buf * B_BUF,
                      lane, wm, wn, acc);
    }
}

// GEMM1: h = tf32( gelu( gather(xt, rev) @ w1t[e] ) )   [K=1024, 32 stages]
__global__ __launch_bounds__(NTHREADS, 2) void gemm1_mma() {
    extern __shared__ uint32_t smem[];
    uint32_t* Bs0 = smem + STAGES * A_BUF;
    int* srev = (int*)(smem + STAGES * (A_BUF + B_BUF));
    uint32_t sbase = (uint32_t)__cvta_generic_to_shared(smem);
    uint32_t sA = sbase, sB = sbase + STAGES * A_BUF * 4;

    int tid = threadIdx.x, lane = tid & 31, wid = tid >> 5;
    int mt = blockIdx.x, ntb = blockIdx.y, e = blockIdx.z;
    const uint32_t* w1e = g_w1t + (size_t)e * D_MODEL * FF_DIM;
    int nb = ntb * BN;
    if (tid < BM) srev[tid] = g_rev[e * CHUNK + mt * BM + tid];
    __syncthreads();

    int wm = wid & 1, wn = wid >> 1;     // 2x2 warps, 64x64 tiles
    float acc[4][8][4];
#pragma unroll
    for (int i = 0; i < 4; i++)
#pragma unroll
        for (int j = 0; j < 8; j++)
#pragma unroll
            for (int c = 0; c < 4; c++) acc[i][j][c] = 0.f;

    gemm_mainloop<true>(g_xt, srev, D_MODEL, w1e + nb, FF_DIM,
                        Bs0, sA, sB, D_MODEL / BKF, tid, lane, wm, wn, acc);

    // Epilogue: GELU + tf32 round -> g_h (u32)
    int hrow0 = e * CHUNK + mt * BM;
#pragma unroll
    for (int m2 = 0; m2 < 4; m2++) {
        int r0 = wm * 64 + m2 * 16 + (lane >> 2);
#pragma unroll
        for (int half = 0; half < 2; half++) {
            uint32_t* hr =
                g_h + (size_t)(hrow0 + r0 + half * 8) * FF_DIM + nb;
#pragma unroll
            for (int n2 = 0; n2 < 8; n2++) {
                int col = wn * 64 + n2 * 8 + 2 * (lane & 3);
                uint2 o;
                o.x = f2tf(gelu_exact(acc[m2][n2][half * 2 + 0]));
                o.y = f2tf(gelu_exact(acc[m2][n2][half * 2 + 1]));
                *(uint2*)(hr + col) = o;
            }
        }
    }
}

// GEMM2: y = (h @ w2t[e]) * sw   [K=4096, 128 stages]
__global__ __launch_bounds__(NTHREADS, 2) void gemm2_mma() {
    extern __shared__ uint32_t smem[];
    uint32_t* Bs0 = smem + STAGES * A_BUF;
    uint32_t sbase = (uint32_t)__cvta_generic_to_shared(smem);
    uint32_t sA = sbase, sB = sbase + STAGES * A_BUF * 4;

    int tid = threadIdx.x, lane = tid & 31, wid = tid >> 5;
    int mt = blockIdx.x, ntb = blockIdx.y, e = blockIdx.z;
    const uint32_t* w2e = g_w2t + (size_t)e * FF_DIM * D_MODEL;
    const uint32_t* Aep = g_h + (size_t)(e * CHUNK + mt * BM) * FF_DIM;
    int nb = ntb * BN;

    int wm = wid & 1, wn = wid >> 1;
    float acc[4][8][4];
#pragma unroll
    for (int i = 0; i < 4; i++)
#pragma unroll
        for (int j = 0; j < 8; j++)
#pragma unroll
            for (int c = 0; c < 4; c++) acc[i][j][c] = 0.f;

    gemm_mainloop<false>(Aep, nullptr, FF_DIM, w2e + nb, D_MODEL,
                         Bs0, sA, sB, FF_DIM / BKF, tid, lane, wm, wn, acc);

    // Epilogue: gate-weight scale -> g_y (sorted order)
    int srow0 = e * CHUNK + mt * BM;
#pragma unroll
    for (int m2 = 0; m2 < 4; m2++) {
        int r0 = wm * 64 + m2 * 16 + (lane >> 2);
#pragma unroll
        for (int half = 0; half < 2; half++) {
            int srow = srow0 + r0 + half * 8;
            float w = g_sw[srow];
            float* yr = g_y + (size_t)srow * D_MODEL + nb;
#pragma unroll
            for (int n2 = 0; n2 < 8; n2++) {
                int col = wn * 64 + n2 * 8 + 2 * (lane & 3);
                float2 o;
                o.x = acc[m2][n2][half * 2 + 0] * w;
                o.y = acc[m2][n2][half * 2 + 1] * w;
                *(float2*)(yr + col) = o;
            }
        }
    }
}

// Combine: out[t] = y[pos(t,0)] + y[pos(t,1)]  (full overwrite, no atomics)
__global__ void combine_kernel(float* __restrict__ out) {
    int t = blockIdx.x;
    int c = threadIdx.x * 4;
    int p0 = g_pos[2 * t], p1 = g_pos[2 * t + 1];
    float4 a = *(const float4*)(g_y + (size_t)p0 * D_MODEL + c);
    float4 b = *(const float4*)(g_y + (size_t)p1 * D_MODEL + c);
    float4 o;
    o.x = a.x + b.x; o.y = a.y + b.y; o.z = a.z + b.z; o.w = a.w + b.w;
    *(float4*)(out + (size_t)t * D_MODEL + c) = o;
}

// ---------------------------------------------------------------------------
extern "C" void kernel_launch(void* const* d_in, const int* in_sizes, int n_in,
                              void* d_out, int out_size) {
    const float* x  = (const float*)d_in[0];   // [4,2048,1024]
    const float* rw = (const float*)d_in[1];   // [8,1024]
    const float* w1 = (const float*)d_in[2];   // [8,1024,4096]
    const float* w2 = (const float*)d_in[3];   // [8,4096,1024]
    float* out = (float*)d_out;                // [4,2048,1024]

    // Idempotent, called every time (no static guards per harness rules)
    cudaFuncSetAttribute(gemm1_mma,
        cudaFuncAttributeMaxDynamicSharedMemorySize, SMEM_BYTES);
    cudaFuncSetAttribute(gemm2_mma,
        cudaFuncAttributeMaxDynamicSharedMemorySize, SMEM_BYTES);

    uint32_t *w1t_p, *w2t_p, *xt_p;
    cudaGetSymbolAddress((void**)&w1t_p, g_w1t);
    cudaGetSymbolAddress((void**)&w2t_p, g_w2t);
    cudaGetSymbolAddress((void**)&xt_p, g_xt);

    // Pre-convert weights + activations to tf32 (RN)
    int nw = NE * D_MODEL * FF_DIM / 4;        // 8.39M float4 each
    conv_tf32_kernel<<<4096, 256>>>((const float4*)w1, (uint4*)w1t_p, nw);
    conv_tf32_kernel<<<4096, 256>>>((const float4*)w2, (uint4*)w2t_p, nw);
    conv_tf32_kernel<<<2048, 256>>>((const float4*)x, (uint4*)xt_p,
                                    N_TOK * D_MODEL / 4);

    router_kernel<<<N_TOK / 8, 256>>>(x, rw);
    sort_kernel<<<1, 256>>>();

    dim3 g1(CHUNK / BM, FF_DIM / BN, NE);      // 16 x 32 x 8
    gemm1_mma<<<g1, NTHREADS, SMEM_BYTES>>>();
    dim3 g2(CHUNK / BM, D_MODEL / BN, NE);     // 16 x 8 x 8
    gemm2_mma<<<g2, NTHREADS, SMEM_BYTES>>>();

    combine_kernel<<<N_TOK, 256>>>(out);
}

// round 13
// speedup vs baseline: 1.6908x; 1.5841x over previous
#include <cuda_runtime.h>
#include <cuda_fp16.h>
#include <math.h>
#include <stdint.h>

// Problem constants (B=4, T=2048, D=1024, FF=4096, E=8, K=2)
#define N_TOK   8192
#define NE      8
#define D_MODEL 1024
#define FF_DIM  4096
#define NK      16384            // N_TOK * 2 expanded rows
#define CHUNK   2048             // NK / NE rows per expert chunk

// Scratch (__device__ globals: allocation-guard-safe)
__device__ __half g_w1h[(size_t)NE * D_MODEL * FF_DIM];  // 67 MB fp16 w1
__device__ __half g_w2h[(size_t)NE * FF_DIM * D_MODEL];  // 67 MB fp16 w2
__device__ __half g_xh[(size_t)N_TOK * D_MODEL];         // 16.8 MB fp16 x
__device__ __half g_h[(size_t)NK * FF_DIM];              // 134 MB fp16 h
__device__ float  g_y[(size_t)NK * D_MODEL];             // 64 MB outputs
__device__ int    g_expert[NK];
__device__ float  g_wflat[NK];
__device__ int    g_rev[NK];
__device__ float  g_sw[NK];
__device__ int    g_pos[NK];                             // inverse perm

// ---------------------------------------------------------------------------
// m16n8k16 fp16 HMMA, fp32 accumulate (baseline PTX, works on compute_103)
__device__ __forceinline__ void mma16n8k16(float* d, const uint32_t* a,
                                           const uint32_t* b) {
    asm volatile(
        "mma.sync.aligned.m16n8k16.row.col.f32.f16.f16.f32 "
        "{%0,%1,%2,%3}, {%4,%5,%6,%7}, {%8,%9}, {%0,%1,%2,%3};"
        : "+f"(d[0]), "+f"(d[1]), "+f"(d[2]), "+f"(d[3])
        : "r"(a[0]), "r"(a[1]), "r"(a[2]), "r"(a[3]), "r"(b[0]), "r"(b[1]));
}
__device__ __forceinline__ void ldsm_x4(uint32_t* r, uint32_t addr) {
    asm volatile(
        "ldmatrix.sync.aligned.m8n8.x4.shared.b16 {%0,%1,%2,%3}, [%4];"
        : "=r"(r[0]), "=r"(r[1]), "=r"(r[2]), "=r"(r[3]) : "r"(addr));
}
__device__ __forceinline__ void ldsm_x4_t(uint32_t* r, uint32_t addr) {
    asm volatile(
        "ldmatrix.sync.aligned.m8n8.x4.trans.shared.b16 {%0,%1,%2,%3}, [%4];"
        : "=r"(r[0]), "=r"(r[1]), "=r"(r[2]), "=r"(r[3]) : "r"(addr));
}
__device__ __forceinline__ void cp16(uint32_t dst, const void* src) {
    asm volatile("cp.async.cg.shared.global [%0], [%1], 16;"
                 :: "r"(dst), "l"(src));
}
#define CP_COMMIT() asm volatile("cp.async.commit_group;" ::: "memory")
#define CP_WAIT(n)  asm volatile("cp.async.wait_group %0;" :: "n"(n) : "memory")

__device__ __forceinline__ float gelu_exact(float v) {
    return 0.5f * v * (1.f + erff(v * 0.70710678118654752f));
}

// ---------------------------------------------------------------------------
// fp32 -> fp16 (RN) streaming conversion: one float4 -> 4 halves (uint2)
__global__ void conv_f16_kernel(const float4* __restrict__ src,
                                uint2* __restrict__ dst, int n4) {
    for (int i = blockIdx.x * blockDim.x + threadIdx.x; i < n4;
         i += gridDim.x * blockDim.x) {
        float4 v = src[i];
        __half2 h0 = __floats2half2_rn(v.x, v.y);
        __half2 h1 = __floats2half2_rn(v.z, v.w);
        uint2 o;
        o.x = *(uint32_t*)&h0;
        o.y = *(uint32_t*)&h1;
        dst[i] = o;
    }
}

// ---------------------------------------------------------------------------
// Router (fp32, exact): logits, top-2, softmax-of-2. One warp per token.
// ---------------------------------------------------------------------------
__global__ void router_kernel(const float* __restrict__ x,
                              const float* __restrict__ rw) {
    int gwarp = (blockIdx.x * blockDim.x + threadIdx.x) >> 5;
    int lane  = threadIdx.x & 31;
    if (gwarp >= N_TOK) return;
    const float* xr = x + (size_t)gwarp * D_MODEL;
    float acc[NE];
#pragma unroll
    for (int e = 0; e < NE; e++) acc[e] = 0.f;
    for (int c = lane; c < D_MODEL; c += 32) {
        float xv = xr[c];
#pragma unroll
        for (int e = 0; e < NE; e++) acc[e] += xv * rw[e * D_MODEL + c];
    }
#pragma unroll
    for (int e = 0; e < NE; e++)
#pragma unroll
        for (int o = 16; o > 0; o >>= 1)
            acc[e] += __shfl_xor_sync(0xffffffffu, acc[e], o);
    if (lane == 0) {
        int i0 = 0; float v0 = acc[0];
#pragma unroll
        for (int e = 1; e < NE; e++) if (acc[e] > v0) { v0 = acc[e]; i0 = e; }
        int i1 = -1; float v1 = -INFINITY;
#pragma unroll
        for (int e = 0; e < NE; e++)
            if (e != i0 && acc[e] > v1) { v1 = acc[e]; i1 = e; }
        float ex = expf(v1 - v0);
        float inv = 1.f / (1.f + ex);
        g_expert[gwarp * 2 + 0] = i0;
        g_expert[gwarp * 2 + 1] = i1;
        g_wflat[gwarp * 2 + 0] = inv;
        g_wflat[gwarp * 2 + 1] = ex * inv;
    }
}

// ---------------------------------------------------------------------------
// Stable counting sort by expert id; also emits inverse permutation g_pos.
// ---------------------------------------------------------------------------
__global__ void sort_kernel() {
    __shared__ int cnt[256][NE];
    __shared__ int base[NE];
    int tid = threadIdx.x;
    int start = tid * 64;
    int my[NE];
#pragma unroll
    for (int e = 0; e < NE; e++) my[e] = 0;
    for (int j = 0; j < 64; j++) my[g_expert[start + j]]++;
#pragma unroll
    for (int e = 0; e < NE; e++) cnt[tid][e] = my[e];
    __syncthreads();
    if (tid < NE) {
        int e = tid, run = 0;
        for (int t = 0; t < 256; t++) { int c = cnt[t][e]; cnt[t][e] = run; run += c; }
        base[e] = run;
    }
    __syncthreads();
    if (tid == 0) {
        int run = 0;
        for (int e = 0; e < NE; e++) { int c = base[e]; base[e] = run; run += c; }
    }
    __syncthreads();
    int off[NE];
#pragma unroll
    for (int e = 0; e < NE; e++) off[e] = base[e] + cnt[tid][e];
    for (int j = 0; j < 64; j++) {
        int i = start + j;
        int e = g_expert[i];
        int pos = off[e]++;
        g_rev[pos] = i >> 1;
        g_sw[pos]  = g_wflat[i];
        g_pos[i]   = pos;
    }
}

// ---------------------------------------------------------------------------
// fp16 m16n8k16 GEMMs, 3-stage cp.async ring, 128 threads (4 warps, 2x2),
// warp tile 64x64. A frags via ldmatrix.x4, B via ldmatrix.x4.trans.
// BK = 64 halves. Pitches (halves): A 72, B 136 -> conflict-free ldmatrix.
// ---------------------------------------------------------------------------
#define BM 128
#define BN 128
#define BKH 64
#define PA 72
#define PB 136
#define STAGES 3
#define NTHREADS 128
#define A_BUF_H (BM * PA)                // 9216 halves (18432 B)
#define B_BUF_H (BKH * PB)               // 8704 halves (17408 B)
#define STAGE_B ((A_BUF_H + B_BUF_H) * 2)
#define SMEM_BYTES (STAGES * STAGE_B + 512)   // 108,032 B

template <bool GATHER>
__device__ __forceinline__ void issue_stage(
    uint32_t sA, uint32_t sB, const __half* __restrict__ Abase,
    const int* __restrict__ srev, size_t lda,
    const __half* __restrict__ Bsrc, size_t ldb, int tid) {
#pragma unroll
    for (int j = 0; j < 8; j++) {        // A: 128 rows x 8 chunks of 8 halves
        int idx = tid + j * NTHREADS;    // 0..1023
        int row = idx >> 3, c8 = (idx & 7) << 3;
        const __half* src = GATHER
            ? Abase + (size_t)srev[row] * lda + c8
            : Abase + (size_t)row * lda + c8;
        cp16(sA + (uint32_t)(row * PA + c8) * 2, src);
    }
#pragma unroll
    for (int j = 0; j < 8; j++) {        // B: 64 k-rows x 16 chunks
        int idx = tid + j * NTHREADS;
        int k = idx >> 4, c8 = (idx & 15) << 3;
        cp16(sB + (uint32_t)(k * PB + c8) * 2, Bsrc + (size_t)k * ldb + c8);
    }
}

// One smem stage: 4 k16 steps x (4 ldsm.x4 + 4 ldsm.x4.trans + 32 HMMA)
__device__ __forceinline__ void compute_stage(
    uint32_t aAddr, uint32_t bAddr,
    int lane, int wm, int wn, float acc[4][8][4]) {
    int g = lane >> 3, tr = lane & 7;
    // A tiles: g0=rows0-7@k0, g1=rows8-15@k0, g2=rows0-7@k8, g3=rows8-15@k8
    uint32_t aLane = aAddr +
        (uint32_t)(((wm * 64 + (g & 1) * 8 + tr) * PA + (g >> 1) * 8) * 2);
    // B tiles (trans): g0=k0-7@n0, g1=k8-15@n0, g2=k0-7@n8, g3=k8-15@n8
    uint32_t bLane = bAddr +
        (uint32_t)((((g & 1) * 8 + tr) * PB + wn * 64 + (g >> 1) * 8) * 2);
#pragma unroll
    for (int k16 = 0; k16 < 4; k16++) {
        uint32_t a[4][4];
#pragma unroll
        for (int m2 = 0; m2 < 4; m2++)
            ldsm_x4(a[m2], aLane + (uint32_t)((m2 * 16 * PA + k16 * 16) * 2));
        uint32_t b[4][4];                // b[nn] = frags for n-tiles 2nn,2nn+1
#pragma unroll
        for (int nn = 0; nn < 4; nn++)
            ldsm_x4_t(b[nn], bLane + (uint32_t)((k16 * 16 * PB + nn * 16) * 2));
#pragma unroll
        for (int m2 = 0; m2 < 4; m2++)
#pragma unroll
            for (int n2 = 0; n2 < 8; n2++)
                mma16n8k16(acc[m2][n2], a[m2], &b[n2 >> 1][(n2 & 1) * 2]);
    }
}

template <bool GATHER>
__device__ __forceinline__ void gemm_mainloop(
    const __half* __restrict__ Abase, const int* __restrict__ srev,
    size_t lda, const __half* __restrict__ Bsrc, size_t ldb,
    uint32_t sA, uint32_t sB,
    int S, int tid, int lane, int wm, int wn, float acc[4][8][4]) {
#pragma unroll
    for (int p = 0; p < STAGES - 1; p++) {
        issue_stage<GATHER>(sA + p * STAGE_B, sB + p * STAGE_B,
                            Abase + p * BKH, srev, lda,
                            Bsrc + (size_t)(p * BKH) * ldb, ldb, tid);
        CP_COMMIT();
    }
    for (int s = 0; s < S; s++) {
        if (s + 1 < S) CP_WAIT(1); else CP_WAIT(0);
        __syncthreads();
        int nx = s + STAGES - 1;
        if (nx < S) {
            int bufn = nx % STAGES;
            issue_stage<GATHER>(sA + bufn * STAGE_B, sB + bufn * STAGE_B,
                                Abase + nx * BKH, srev, lda,
                                Bsrc + (size_t)(nx * BKH) * ldb, ldb, tid);
            CP_COMMIT();
        }
        int buf = s % STAGES;
        compute_stage(sA + buf * STAGE_B, sB + buf * STAGE_B,
                      lane, wm, wn, acc);
    }
}

// GEMM1: h = f16( gelu( gather(xh, rev) @ w1h[e] ) )   [K=1024, 16 stages]
__global__ __launch_bounds__(NTHREADS, 2) void gemm1_mma() {
    extern __shared__ uint32_t smem[];
    int* srev = (int*)((char*)smem + STAGES * STAGE_B);
    uint32_t sbase = (uint32_t)__cvta_generic_to_shared(smem);
    uint32_t sA = sbase, sB = sbase + A_BUF_H * 2;

    int tid = threadIdx.x, lane = tid & 31, wid = tid >> 5;
    int mt = blockIdx.x, ntb = blockIdx.y, e = blockIdx.z;
    const __half* w1e = g_w1h + (size_t)e * D_MODEL * FF_DIM;
    int nb = ntb * BN;
    if (tid < BM) srev[tid] = g_rev[e * CHUNK + mt * BM + tid];
    __syncthreads();

    int wm = wid & 1, wn = wid >> 1;     // 2x2 warps, 64x64 tiles
    float acc[4][8][4];
#pragma unroll
    for (int i = 0; i < 4; i++)
#pragma unroll
        for (int j = 0; j < 8; j++)
#pragma unroll
            for (int c = 0; c < 4; c++) acc[i][j][c] = 0.f;

    gemm_mainloop<true>(g_xh, srev, D_MODEL, w1e + nb, FF_DIM,
                        sA, sB, D_MODEL / BKH, tid, lane, wm, wn, acc);

    // Epilogue: GELU -> g_h (fp16 RN)
    int hrow0 = e * CHUNK + mt * BM;
#pragma unroll
    for (int m2 = 0; m2 < 4; m2++) {
        int r0 = wm * 64 + m2 * 16 + (lane >> 2);
#pragma unroll
        for (int half = 0; half < 2; half++) {
            __half* hr = g_h + (size_t)(hrow0 + r0 + half * 8) * FF_DIM + nb;
#pragma unroll
            for (int n2 = 0; n2 < 8; n2++) {
                int col = wn * 64 + n2 * 8 + 2 * (lane & 3);
                __half2 o = __floats2half2_rn(
                    gelu_exact(acc[m2][n2][half * 2 + 0]),
                    gelu_exact(acc[m2][n2][half * 2 + 1]));
                *(__half2*)(hr + col) = o;
            }
        }
    }
}

// GEMM2: y = (h @ w2h[e]) * sw   [K=4096, 64 stages]
__global__ __launch_bounds__(NTHREADS, 2) void gemm2_mma() {
    extern __shared__ uint32_t smem[];
    uint32_t sbase = (uint32_t)__cvta_generic_to_shared(smem);
    uint32_t sA = sbase, sB = sbase + A_BUF_H * 2;

    int tid = threadIdx.x, lane = tid & 31, wid = tid >> 5;
    int mt = blockIdx.x, ntb = blockIdx.y, e = blockIdx.z;
    const __half* w2e = g_w2h + (size_t)e * FF_DIM * D_MODEL;
    const __half* Aep = g_h + (size_t)(e * CHUNK + mt * BM) * FF_DIM;
    int nb = ntb * BN;

    int wm = wid & 1, wn = wid >> 1;
    float acc[4][8][4];
#pragma unroll
    for (int i = 0; i < 4; i++)
#pragma unroll
        for (int j = 0; j < 8; j++)
#pragma unroll
            for (int c = 0; c < 4; c++) acc[i][j][c] = 0.f;

    gemm_mainloop<false>(Aep, nullptr, FF_DIM, w2e + nb, D_MODEL,
                         sA, sB, FF_DIM / BKH, tid, lane, wm, wn, acc);

    // Epilogue: gate-weight scale -> g_y (sorted order, fp32)
    int srow0 = e * CHUNK + mt * BM;
#pragma unroll
    for (int m2 = 0; m2 < 4; m2++) {
        int r0 = wm * 64 + m2 * 16 + (lane >> 2);
#pragma unroll
        for (int half = 0; half < 2; half++) {
            int srow = srow0 + r0 + half * 8;
            float w = g_sw[srow];
            float* yr = g_y + (size_t)srow * D_MODEL + nb;
#pragma unroll
            for (int n2 = 0; n2 < 8; n2++) {
                int col = wn * 64 + n2 * 8 + 2 * (lane & 3);
                float2 o;
                o.x = acc[m2][n2][half * 2 + 0] * w;
                o.y = acc[m2][n2][half * 2 + 1] * w;
                *(float2*)(yr + col) = o;
            }
        }
    }
}

// Combine: out[t] = y[pos(t,0)] + y[pos(t,1)]  (full overwrite, no atomics)
__global__ void combine_kernel(float* __restrict__ out) {
    int t = blockIdx.x;
    int c = threadIdx.x * 4;
    int p0 = g_pos[2 * t], p1 = g_pos[2 * t + 1];
    float4 a = *(const float4*)(g_y + (size_t)p0 * D_MODEL + c);
    float4 b = *(const float4*)(g_y + (size_t)p1 * D_MODEL + c);
    float4 o;
    o.x = a.x + b.x; o.y = a.y + b.y; o.z = a.z + b.z; o.w = a.w + b.w;
    *(float4*)(out + (size_t)t * D_MODEL + c) = o;
}

// ---------------------------------------------------------------------------
extern "C" void kernel_launch(void* const* d_in, const int* in_sizes, int n_in,
                              void* d_out, int out_size) {
    const float* x  = (const float*)d_in[0];   // [4,2048,1024]
    const float* rw = (const float*)d_in[1];   // [8,1024]
    const float* w1 = (const float*)d_in[2];   // [8,1024,4096]
    const float* w2 = (const float*)d_in[3];   // [8,4096,1024]
    float* out = (float*)d_out;                // [4,2048,1024]

    // Idempotent, called every time (no static guards per harness rules)
    cudaFuncSetAttribute(gemm1_mma,
        cudaFuncAttributeMaxDynamicSharedMemorySize, SMEM_BYTES);
    cudaFuncSetAttribute(gemm2_mma,
        cudaFuncAttributeMaxDynamicSharedMemorySize, SMEM_BYTES);

    __half *w1h_p, *w2h_p, *xh_p;
    cudaGetSymbolAddress((void**)&w1h_p, g_w1h);
    cudaGetSymbolAddress((void**)&w2h_p, g_w2h);
    cudaGetSymbolAddress((void**)&xh_p, g_xh);

    // Pre-convert weights + activations to fp16 (RN)
    int nw = NE * D_MODEL * FF_DIM / 4;        // 8.39M float4 each
    conv_f16_kernel<<<4096, 256>>>((const float4*)w1, (uint2*)w1h_p, nw);
    conv_f16_kernel<<<4096, 256>>>((const float4*)w2, (uint2*)w2h_p, nw);
    conv_f16_kernel<<<2048, 256>>>((const float4*)x, (uint2*)xh_p,
                                   N_TOK * D_MODEL / 4);

    router_kernel<<<N_TOK / 8, 256>>>(x, rw);
    sort_kernel<<<1, 256>>>();

    dim3 g1(CHUNK / BM, FF_DIM / BN, NE);      // 16 x 32 x 8
    gemm1_mma<<<g1, NTHREADS, SMEM_BYTES>>>();
    dim3 g2(CHUNK / BM, D_MODEL / BN, NE);     // 16 x 8 x 8
    gemm2_mma<<<g2, NTHREADS, SMEM_BYTES>>>();

    combine_kernel<<<N_TOK, 256>>>(out);
}

// round 14
// speedup vs baseline: 1.8108x; 1.0710x over previous
#include <cuda_runtime.h>
#include <cuda_fp16.h>
#include <math.h>
#include <stdint.h>

// Problem constants (B=4, T=2048, D=1024, FF=4096, E=8, K=2)
#define N_TOK   8192
#define NE      8
#define D_MODEL 1024
#define FF_DIM  4096
#define NK      16384            // N_TOK * 2 expanded rows
#define CHUNK   2048             // NK / NE rows per expert chunk

// Scratch (__device__ globals: allocation-guard-safe)
__device__ __half g_w1h[(size_t)NE * D_MODEL * FF_DIM];  // 67 MB fp16 w1
__device__ __half g_w2h[(size_t)NE * FF_DIM * D_MODEL];  // 67 MB fp16 w2
__device__ __half g_xh[(size_t)N_TOK * D_MODEL];         // 16.8 MB fp16 x
__device__ __half g_h[(size_t)NK * FF_DIM];              // 134 MB fp16 h
__device__ float  g_y[(size_t)NK * D_MODEL];             // 64 MB outputs
__device__ int    g_expert[NK];
__device__ float  g_wflat[NK];
__device__ int    g_rev[NK];
__device__ float  g_sw[NK];
__device__ int    g_pos[NK];                             // inverse perm

// ---------------------------------------------------------------------------
// m16n8k16 fp16 HMMA, fp32 accumulate (baseline PTX, works on compute_103)
__device__ __forceinline__ void mma16n8k16(float* d, const uint32_t* a,
                                           const uint32_t* b) {
    asm volatile(
        "mma.sync.aligned.m16n8k16.row.col.f32.f16.f16.f32 "
        "{%0,%1,%2,%3}, {%4,%5,%6,%7}, {%8,%9}, {%0,%1,%2,%3};"
        : "+f"(d[0]), "+f"(d[1]), "+f"(d[2]), "+f"(d[3])
        : "r"(a[0]), "r"(a[1]), "r"(a[2]), "r"(a[3]), "r"(b[0]), "r"(b[1]));
}
__device__ __forceinline__ void ldsm_x4(uint32_t* r, uint32_t addr) {
    asm volatile(
        "ldmatrix.sync.aligned.m8n8.x4.shared.b16 {%0,%1,%2,%3}, [%4];"
        : "=r"(r[0]), "=r"(r[1]), "=r"(r[2]), "=r"(r[3]) : "r"(addr));
}
__device__ __forceinline__ void ldsm_x4_t(uint32_t* r, uint32_t addr) {
    asm volatile(
        "ldmatrix.sync.aligned.m8n8.x4.trans.shared.b16 {%0,%1,%2,%3}, [%4];"
        : "=r"(r[0]), "=r"(r[1]), "=r"(r[2]), "=r"(r[3]) : "r"(addr));
}
__device__ __forceinline__ void cp16(uint32_t dst, const void* src) {
    asm volatile("cp.async.cg.shared.global [%0], [%1], 16;"
                 :: "r"(dst), "l"(src));
}
#define CP_COMMIT() asm volatile("cp.async.commit_group;" ::: "memory")
#define CP_WAIT(n)  asm volatile("cp.async.wait_group %0;" :: "n"(n) : "memory")

__device__ __forceinline__ float gelu_exact(float v) {
    return 0.5f * v * (1.f + erff(v * 0.70710678118654752f));
}

// ---------------------------------------------------------------------------
// fp32 -> fp16 (RN) streaming conversion: one float4 -> 4 halves (uint2)
__global__ void conv_f16_kernel(const float4* __restrict__ src,
                                uint2* __restrict__ dst, int n4) {
    for (int i = blockIdx.x * blockDim.x + threadIdx.x; i < n4;
         i += gridDim.x * blockDim.x) {
        float4 v = src[i];
        __half2 h0 = __floats2half2_rn(v.x, v.y);
        __half2 h1 = __floats2half2_rn(v.z, v.w);
        uint2 o;
        o.x = *(uint32_t*)&h0;
        o.y = *(uint32_t*)&h1;
        dst[i] = o;
    }
}

// ---------------------------------------------------------------------------
// Router (fp32, exact): logits, top-2, softmax-of-2. One warp per token.
// ---------------------------------------------------------------------------
__global__ void router_kernel(const float* __restrict__ x,
                              const float* __restrict__ rw) {
    int gwarp = (blockIdx.x * blockDim.x + threadIdx.x) >> 5;
    int lane  = threadIdx.x & 31;
    if (gwarp >= N_TOK) return;
    const float* xr = x + (size_t)gwarp * D_MODEL;
    float acc[NE];
#pragma unroll
    for (int e = 0; e < NE; e++) acc[e] = 0.f;
    for (int c = lane; c < D_MODEL; c += 32) {
        float xv = xr[c];
#pragma unroll
        for (int e = 0; e < NE; e++) acc[e] += xv * rw[e * D_MODEL + c];
    }
#pragma unroll
    for (int e = 0; e < NE; e++)
#pragma unroll
        for (int o = 16; o > 0; o >>= 1)
            acc[e] += __shfl_xor_sync(0xffffffffu, acc[e], o);
    if (lane == 0) {
        int i0 = 0; float v0 = acc[0];
#pragma unroll
        for (int e = 1; e < NE; e++) if (acc[e] > v0) { v0 = acc[e]; i0 = e; }
        int i1 = -1; float v1 = -INFINITY;
#pragma unroll
        for (int e = 0; e < NE; e++)
            if (e != i0 && acc[e] > v1) { v1 = acc[e]; i1 = e; }
        float ex = expf(v1 - v0);
        float inv = 1.f / (1.f + ex);
        g_expert[gwarp * 2 + 0] = i0;
        g_expert[gwarp * 2 + 1] = i1;
        g_wflat[gwarp * 2 + 0] = inv;
        g_wflat[gwarp * 2 + 1] = ex * inv;
    }
}

// ---------------------------------------------------------------------------
// Stable counting sort by expert id; also emits inverse permutation g_pos.
// ---------------------------------------------------------------------------
__global__ void sort_kernel() {
    __shared__ int cnt[256][NE];
    __shared__ int base[NE];
    int tid = threadIdx.x;
    int start = tid * 64;
    int my[NE];
#pragma unroll
    for (int e = 0; e < NE; e++) my[e] = 0;
    for (int j = 0; j < 64; j++) my[g_expert[start + j]]++;
#pragma unroll
    for (int e = 0; e < NE; e++) cnt[tid][e] = my[e];
    __syncthreads();
    if (tid < NE) {
        int e = tid, run = 0;
        for (int t = 0; t < 256; t++) { int c = cnt[t][e]; cnt[t][e] = run; run += c; }
        base[e] = run;
    }
    __syncthreads();
    if (tid == 0) {
        int run = 0;
        for (int e = 0; e < NE; e++) { int c = base[e]; base[e] = run; run += c; }
    }
    __syncthreads();
    int off[NE];
#pragma unroll
    for (int e = 0; e < NE; e++) off[e] = base[e] + cnt[tid][e];
    for (int j = 0; j < 64; j++) {
        int i = start + j;
        int e = g_expert[i];
        int pos = off[e]++;
        g_rev[pos] = i >> 1;
        g_sw[pos]  = g_wflat[i];
        g_pos[i]   = pos;
    }
}

// ---------------------------------------------------------------------------
// fp16 m16n8k16 GEMMs, 3-stage cp.async ring, 256 threads (8 warps, 2x4),
// warp tile 64x32. A frags via ldmatrix.x4, B via ldmatrix.x4.trans.
// BK = 64 halves. Pitches (halves): A 72, B 136 -> conflict-free ldmatrix.
// 2 CTAs/SM -> 16 warps/SM (4 per SMSP) for latency hiding.
// ---------------------------------------------------------------------------
#define BM 128
#define BN 128
#define BKH 64
#define PA 72
#define PB 136
#define STAGES 3
#define NTHREADS 256
#define A_BUF_H (BM * PA)                // 9216 halves (18432 B)
#define B_BUF_H (BKH * PB)               // 8704 halves (17408 B)
#define STAGE_B ((A_BUF_H + B_BUF_H) * 2)
#define SMEM_BYTES (STAGES * STAGE_B + 512)   // 108,032 B

template <bool GATHER>
__device__ __forceinline__ void issue_stage(
    uint32_t sA, uint32_t sB, const __half* __restrict__ Abase,
    const int* __restrict__ srev, size_t lda,
    const __half* __restrict__ Bsrc, size_t ldb, int tid) {
#pragma unroll
    for (int j = 0; j < 4; j++) {        // A: 128 rows x 8 chunks of 8 halves
        int idx = tid + j * NTHREADS;    // 0..1023
        int row = idx >> 3, c8 = (idx & 7) << 3;
        const __half* src = GATHER
            ? Abase + (size_t)srev[row] * lda + c8
            : Abase + (size_t)row * lda + c8;
        cp16(sA + (uint32_t)(row * PA + c8) * 2, src);
    }
#pragma unroll
    for (int j = 0; j < 4; j++) {        // B: 64 k-rows x 16 chunks
        int idx = tid + j * NTHREADS;
        int k = idx >> 4, c8 = (idx & 15) << 3;
        cp16(sB + (uint32_t)(k * PB + c8) * 2, Bsrc + (size_t)k * ldb + c8);
    }
}

// One smem stage: 4 k16 steps x (4 A-ldsm + 2 B-ldsm + 16 HMMA)
// Warp tile 64(M) x 32(N): 4 m-tiles x 4 n-tiles.
__device__ __forceinline__ void compute_stage(
    uint32_t aAddr, uint32_t bAddr,
    int lane, int wm, int wn, float acc[4][4][4]) {
    int g = lane >> 3, tr = lane & 7;
    // A tiles: g0=rows0-7@k0, g1=rows8-15@k0, g2=rows0-7@k8, g3=rows8-15@k8
    uint32_t aLane = aAddr +
        (uint32_t)(((wm * 64 + (g & 1) * 8 + tr) * PA + (g >> 1) * 8) * 2);
    // B tiles (trans): g0=k0-7@n0, g1=k8-15@n0, g2=k0-7@n8, g3=k8-15@n8
    uint32_t bLane = bAddr +
        (uint32_t)((((g & 1) * 8 + tr) * PB + wn * 32 + (g >> 1) * 8) * 2);
#pragma unroll
    for (int k16 = 0; k16 < 4; k16++) {
        uint32_t a[4][4];
#pragma unroll
        for (int m2 = 0; m2 < 4; m2++)
            ldsm_x4(a[m2], aLane + (uint32_t)((m2 * 16 * PA + k16 * 16) * 2));
        uint32_t b[2][4];                // b[nn] = frags for n-tiles 2nn,2nn+1
#pragma unroll
        for (int nn = 0; nn < 2; nn++)
            ldsm_x4_t(b[nn], bLane + (uint32_t)((k16 * 16 * PB + nn * 16) * 2));
#pragma unroll
        for (int m2 = 0; m2 < 4; m2++)
#pragma unroll
            for (int n2 = 0; n2 < 4; n2++)
                mma16n8k16(acc[m2][n2], a[m2], &b[n2 >> 1][(n2 & 1) * 2]);
    }
}

template <bool GATHER>
__device__ __forceinline__ void gemm_mainloop(
    const __half* __restrict__ Abase, const int* __restrict__ srev,
    size_t lda, const __half* __restrict__ Bsrc, size_t ldb,
    uint32_t sA, uint32_t sB,
    int S, int tid, int lane, int wm, int wn, float acc[4][4][4]) {
#pragma unroll
    for (int p = 0; p < STAGES - 1; p++) {
        issue_stage<GATHER>(sA + p * STAGE_B, sB + p * STAGE_B,
                            Abase + p * BKH, srev, lda,
                            Bsrc + (size_t)(p * BKH) * ldb, ldb, tid);
        CP_COMMIT();
    }
    for (int s = 0; s < S; s++) {
        if (s + 1 < S) CP_WAIT(1); else CP_WAIT(0);
        __syncthreads();
        int nx = s + STAGES - 1;
        if (nx < S) {
            int bufn = nx % STAGES;
            issue_stage<GATHER>(sA + bufn * STAGE_B, sB + bufn * STAGE_B,
                                Abase + nx * BKH, srev, lda,
                                Bsrc + (size_t)(nx * BKH) * ldb, ldb, tid);
            CP_COMMIT();
        }
        int buf = s % STAGES;
        compute_stage(sA + buf * STAGE_B, sB + buf * STAGE_B,
                      lane, wm, wn, acc);
    }
}

// GEMM1: h = f16( gelu( gather(xh, rev) @ w1h[e] ) )   [K=1024, 16 stages]
__global__ __launch_bounds__(NTHREADS, 2) void gemm1_mma() {
    extern __shared__ uint32_t smem[];
    int* srev = (int*)((char*)smem + STAGES * STAGE_B);
    uint32_t sbase = (uint32_t)__cvta_generic_to_shared(smem);
    uint32_t sA = sbase, sB = sbase + A_BUF_H * 2;

    int tid = threadIdx.x, lane = tid & 31, wid = tid >> 5;
    int mt = blockIdx.x, ntb = blockIdx.y, e = blockIdx.z;
    const __half* w1e = g_w1h + (size_t)e * D_MODEL * FF_DIM;
    int nb = ntb * BN;
    if (tid < BM) srev[tid] = g_rev[e * CHUNK + mt * BM + tid];
    __syncthreads();

    int wm = wid & 1, wn = wid >> 1;     // 2(m) x 4(n) warps, 64x32 tiles
    float acc[4][4][4];
#pragma unroll
    for (int i = 0; i < 4; i++)
#pragma unroll
        for (int j = 0; j < 4; j++)
#pragma unroll
            for (int c = 0; c < 4; c++) acc[i][j][c] = 0.f;

    gemm_mainloop<true>(g_xh, srev, D_MODEL, w1e + nb, FF_DIM,
                        sA, sB, D_MODEL / BKH, tid, lane, wm, wn, acc);

    // Epilogue: GELU -> g_h (fp16 RN)
    int hrow0 = e * CHUNK + mt * BM;
#pragma unroll
    for (int m2 = 0; m2 < 4; m2++) {
        int r0 = wm * 64 + m2 * 16 + (lane >> 2);
#pragma unroll
        for (int half = 0; half < 2; half++) {
            __half* hr = g_h + (size_t)(hrow0 + r0 + half * 8) * FF_DIM + nb;
#pragma unroll
            for (int n2 = 0; n2 < 4; n2++) {
                int col = wn * 32 + n2 * 8 + 2 * (lane & 3);
                __half2 o = __floats2half2_rn(
                    gelu_exact(acc[m2][n2][half * 2 + 0]),
                    gelu_exact(acc[m2][n2][half * 2 + 1]));
                *(__half2*)(hr + col) = o;
            }
        }
    }
}

// GEMM2: y = (h @ w2h[e]) * sw   [K=4096, 64 stages]
__global__ __launch_bounds__(NTHREADS, 2) void gemm2_mma() {
    extern __shared__ uint32_t smem[];
    uint32_t sbase = (uint32_t)__cvta_generic_to_shared(smem);
    uint32_t sA = sbase, sB = sbase + A_BUF_H * 2;

    int tid = threadIdx.x, lane = tid & 31, wid = tid >> 5;
    int mt = blockIdx.x, ntb = blockIdx.y, e = blockIdx.z;
    const __half* w2e = g_w2h + (size_t)e * FF_DIM * D_MODEL;
    const __half* Aep = g_h + (size_t)(e * CHUNK + mt * BM) * FF_DIM;
    int nb = ntb * BN;

    int wm = wid & 1, wn = wid >> 1;
    float acc[4][4][4];
#pragma unroll
    for (int i = 0; i < 4; i++)
#pragma unroll
        for (int j = 0; j < 4; j++)
#pragma unroll
            for (int c = 0; c < 4; c++) acc[i][j][c] = 0.f;

    gemm_mainloop<false>(Aep, nullptr, FF_DIM, w2e + nb, D_MODEL,
                         sA, sB, FF_DIM / BKH, tid, lane, wm, wn, acc);

    // Epilogue: gate-weight scale -> g_y (sorted order, fp32)
    int srow0 = e * CHUNK + mt * BM;
#pragma unroll
    for (int m2 = 0; m2 < 4; m2++) {
        int r0 = wm * 64 + m2 * 16 + (lane >> 2);
#pragma unroll
        for (int half = 0; half < 2; half++) {
            int srow = srow0 + r0 + half * 8;
            float w = g_sw[srow];
            float* yr = g_y + (size_t)srow * D_MODEL + nb;
#pragma unroll
            for (int n2 = 0; n2 < 4; n2++) {
                int col = wn * 32 + n2 * 8 + 2 * (lane & 3);
                float2 o;
                o.x = acc[m2][n2][half * 2 + 0] * w;
                o.y = acc[m2][n2][half * 2 + 1] * w;
                *(float2*)(yr + col) = o;
            }
        }
    }
}

// Combine: out[t] = y[pos(t,0)] + y[pos(t,1)]  (full overwrite, no atomics)
__global__ void combine_kernel(float* __restrict__ out) {
    int t = blockIdx.x;
    int c = threadIdx.x * 4;
    int p0 = g_pos[2 * t], p1 = g_pos[2 * t + 1];
    float4 a = *(const float4*)(g_y + (size_t)p0 * D_MODEL + c);
    float4 b = *(const float4*)(g_y + (size_t)p1 * D_MODEL + c);
    float4 o;
    o.x = a.x + b.x; o.y = a.y + b.y; o.z = a.z + b.z; o.w = a.w + b.w;
    *(float4*)(out + (size_t)t * D_MODEL + c) = o;
}

// ---------------------------------------------------------------------------
extern "C" void kernel_launch(void* const* d_in, const int* in_sizes, int n_in,
                              void* d_out, int out_size) {
    const float* x  = (const float*)d_in[0];   // [4,2048,1024]
    const float* rw = (const float*)d_in[1];   // [8,1024]
    const float* w1 = (const float*)d_in[2];   // [8,1024,4096]
    const float* w2 = (const float*)d_in[3];   // [8,4096,1024]
    float* out = (float*)d_out;                // [4,2048,1024]

    // Idempotent, called every time (no static guards per harness rules)
    cudaFuncSetAttribute(gemm1_mma,
        cudaFuncAttributeMaxDynamicSharedMemorySize, SMEM_BYTES);
    cudaFuncSetAttribute(gemm2_mma,
        cudaFuncAttributeMaxDynamicSharedMemorySize, SMEM_BYTES);

    __half *w1h_p, *w2h_p, *xh_p;
    cudaGetSymbolAddress((void**)&w1h_p, g_w1h);
    cudaGetSymbolAddress((void**)&w2h_p, g_w2h);
    cudaGetSymbolAddress((void**)&xh_p, g_xh);

    // Pre-convert weights + activations to fp16 (RN)
    int nw = NE * D_MODEL * FF_DIM / 4;        // 8.39M float4 each
    conv_f16_kernel<<<4096, 256>>>((const float4*)w1, (uint2*)w1h_p, nw);
    conv_f16_kernel<<<4096, 256>>>((const float4*)w2, (uint2*)w2h_p, nw);
    conv_f16_kernel<<<2048, 256>>>((const float4*)x, (uint2*)xh_p,
                                   N_TOK * D_MODEL / 4);

    router_kernel<<<N_TOK / 8, 256>>>(x, rw);
    sort_kernel<<<1, 256>>>();

    dim3 g1(CHUNK / BM, FF_DIM / BN, NE);      // 16 x 32 x 8
    gemm1_mma<<<g1, NTHREADS, SMEM_BYTES>>>();
    dim3 g2(CHUNK / BM, D_MODEL / BN, NE);     // 16 x 8 x 8
    gemm2_mma<<<g2, NTHREADS, SMEM_BYTES>>>();

    combine_kernel<<<N_TOK, 256>>>(out);
}

// round 17
// speedup vs baseline: 1.8817x; 1.0391x over previous
#include <cuda_runtime.h>
#include <cuda_fp16.h>
#include <math.h>
#include <stdint.h>

// Problem constants (B=4, T=2048, D=1024, FF=4096, E=8, K=2)
#define N_TOK   8192
#define NE      8
#define D_MODEL 1024
#define FF_DIM  4096
#define NK      16384            // N_TOK * 2 expanded rows
#define CHUNK   2048             // NK / NE rows per expert chunk

// Scratch (__device__ globals: allocation-guard-safe)
__device__ __half g_w1h[(size_t)NE * D_MODEL * FF_DIM];  // 67 MB fp16 w1
__device__ __half g_w2h[(size_t)NE * FF_DIM * D_MODEL];  // 67 MB fp16 w2
__device__ __half g_xh[(size_t)N_TOK * D_MODEL];         // 16.8 MB fp16 x
__device__ __half g_h[(size_t)NK * FF_DIM];              // 134 MB fp16 h
__device__ int    g_expert[NK];
__device__ float  g_wflat[NK];
__device__ int    g_rev[NK];
__device__ float  g_sw[NK];

// ---------------------------------------------------------------------------
// m16n8k16 fp16 HMMA, fp32 accumulate (baseline PTX, works on compute_103)
__device__ __forceinline__ void mma16n8k16(float* d, const uint32_t* a,
                                           const uint32_t* b) {
    asm volatile(
        "mma.sync.aligned.m16n8k16.row.col.f32.f16.f16.f32 "
        "{%0,%1,%2,%3}, {%4,%5,%6,%7}, {%8,%9}, {%0,%1,%2,%3};"
        : "+f"(d[0]), "+f"(d[1]), "+f"(d[2]), "+f"(d[3])
        : "r"(a[0]), "r"(a[1]), "r"(a[2]), "r"(a[3]), "r"(b[0]), "r"(b[1]));
}
__device__ __forceinline__ void ldsm_x4(uint32_t* r, uint32_t addr) {
    asm volatile(
        "ldmatrix.sync.aligned.m8n8.x4.shared.b16 {%0,%1,%2,%3}, [%4];"
        : "=r"(r[0]), "=r"(r[1]), "=r"(r[2]), "=r"(r[3]) : "r"(addr));
}
__device__ __forceinline__ void ldsm_x4_t(uint32_t* r, uint32_t addr) {
    asm volatile(
        "ldmatrix.sync.aligned.m8n8.x4.trans.shared.b16 {%0,%1,%2,%3}, [%4];"
        : "=r"(r[0]), "=r"(r[1]), "=r"(r[2]), "=r"(r[3]) : "r"(addr));
}
__device__ __forceinline__ void cp16(uint32_t dst, const void* src) {
    asm volatile("cp.async.cg.shared.global [%0], [%1], 16;"
                 :: "r"(dst), "l"(src));
}
#define CP_COMMIT() asm volatile("cp.async.commit_group;" ::: "memory")
#define CP_WAIT(n)  asm volatile("cp.async.wait_group %0;" :: "n"(n) : "memory")

__device__ __forceinline__ float gelu_exact(float v) {
    return 0.5f * v * (1.f + erff(v * 0.70710678118654752f));
}

// ---------------------------------------------------------------------------
// fp32 -> fp16 (RN) streaming conversion: one float4 -> 4 halves (uint2)
__global__ void conv_f16_kernel(const float4* __restrict__ src,
                                uint2* __restrict__ dst, int n4) {
    for (int i = blockIdx.x * blockDim.x + threadIdx.x; i < n4;
         i += gridDim.x * blockDim.x) {
        float4 v = src[i];
        __half2 h0 = __floats2half2_rn(v.x, v.y);
        __half2 h1 = __floats2half2_rn(v.z, v.w);
        uint2 o;
        o.x = *(uint32_t*)&h0;
        o.y = *(uint32_t*)&h1;
        dst[i] = o;
    }
}

// Zero the (0xAA-poisoned) output before atomic scatter-add.
__global__ void zero_kernel(float4* __restrict__ out, int n4) {
    int i = blockIdx.x * blockDim.x + threadIdx.x;
    if (i < n4) out[i] = make_float4(0.f, 0.f, 0.f, 0.f);
}

// ---------------------------------------------------------------------------
// Router (fp32, exact) + fused x->fp16 conversion.
// One warp per token: float4 loads, 8 expert dots, top-2 softmax;
// also writes the token row into g_xh (fp16 RN).
// ---------------------------------------------------------------------------
__global__ void router_kernel(const float4* __restrict__ x4,
                              const float4* __restrict__ rw4,
                              uint2* __restrict__ xh4) {
    int gwarp = (blockIdx.x * blockDim.x + threadIdx.x) >> 5;
    int lane  = threadIdx.x & 31;
    if (gwarp >= N_TOK) return;
    const int R4 = D_MODEL / 4;            // 256 float4 per row
    const float4* xr = x4 + (size_t)gwarp * R4;
    uint2* xo = xh4 + (size_t)gwarp * R4;

    float acc[NE];
#pragma unroll
    for (int e = 0; e < NE; e++) acc[e] = 0.f;
#pragma unroll
    for (int i = 0; i < 8; i++) {
        int c4 = i * 32 + lane;
        float4 v = xr[c4];
        __half2 h0 = __floats2half2_rn(v.x, v.y);
        __half2 h1 = __floats2half2_rn(v.z, v.w);
        uint2 o;
        o.x = *(uint32_t*)&h0;
        o.y = *(uint32_t*)&h1;
        xo[c4] = o;
#pragma unroll
        for (int e = 0; e < NE; e++) {
            float4 w = rw4[e * R4 + c4];
            acc[e] += v.x * w.x + v.y * w.y + v.z * w.z + v.w * w.w;
        }
    }
#pragma unroll
    for (int e = 0; e < NE; e++)
#pragma unroll
        for (int o = 16; o > 0; o >>= 1)
            acc[e] += __shfl_xor_sync(0xffffffffu, acc[e], o);
    if (lane == 0) {
        int i0 = 0; float v0 = acc[0];
#pragma unroll
        for (int e = 1; e < NE; e++) if (acc[e] > v0) { v0 = acc[e]; i0 = e; }
        int i1 = -1; float v1 = -INFINITY;
#pragma unroll
        for (int e = 0; e < NE; e++)
            if (e != i0 && acc[e] > v1) { v1 = acc[e]; i1 = e; }
        float ex = expf(v1 - v0);
        float inv = 1.f / (1.f + ex);
        g_expert[gwarp * 2 + 0] = i0;
        g_expert[gwarp * 2 + 1] = i1;
        g_wflat[gwarp * 2 + 0] = inv;
        g_wflat[gwarp * 2 + 1] = ex * inv;
    }
}

// ---------------------------------------------------------------------------
// Stable counting sort by expert id -> g_rev (token per slot), g_sw (gates).
// ---------------------------------------------------------------------------
__global__ void sort_kernel() {
    __shared__ int cnt[256][NE];
    __shared__ int base[NE];
    int tid = threadIdx.x;
    int start = tid * 64;
    int my[NE];
#pragma unroll
    for (int e = 0; e < NE; e++) my[e] = 0;
    for (int j = 0; j < 64; j++) my[g_expert[start + j]]++;
#pragma unroll
    for (int e = 0; e < NE; e++) cnt[tid][e] = my[e];
    __syncthreads();
    if (tid < NE) {
        int e = tid, run = 0;
        for (int t = 0; t < 256; t++) { int c = cnt[t][e]; cnt[t][e] = run; run += c; }
        base[e] = run;
    }
    __syncthreads();
    if (tid == 0) {
        int run = 0;
        for (int e = 0; e < NE; e++) { int c = base[e]; base[e] = run; run += c; }
    }
    __syncthreads();
    int off[NE];
#pragma unroll
    for (int e = 0; e < NE; e++) off[e] = base[e] + cnt[tid][e];
    for (int j = 0; j < 64; j++) {
        int i = start + j;
        int e = g_expert[i];
        int pos = off[e]++;
        g_rev[pos] = i >> 1;
        g_sw[pos]  = g_wflat[i];
    }
}

// ---------------------------------------------------------------------------
// fp16 m16n8k16 GEMMs, 3-stage cp.async ring, 256 threads (8 warps, 2x4),
// warp tile 64x32. A frags via ldmatrix.x4, B via ldmatrix.x4.trans.
// BK = 64 halves. Pitches (halves): A 72, B 136 -> conflict-free ldmatrix.
// 2 CTAs/SM -> 16 warps/SM (4 per SMSP).
// ---------------------------------------------------------------------------
#define BM 128
#define BN 128
#define BKH 64
#define PA 72
#define PB 136
#define STAGES 3
#define NTHREADS 256
#define A_BUF_H (BM * PA)                // 9216 halves (18432 B)
#define B_BUF_H (BKH * PB)               // 8704 halves (17408 B)
#define STAGE_B ((A_BUF_H + B_BUF_H) * 2)
#define SMEM_BYTES (STAGES * STAGE_B + 512)   // 108,032 B

template <bool GATHER>
__device__ __forceinline__ void issue_stage(
    uint32_t sA, uint32_t sB, const __half* __restrict__ Abase,
    const int* __restrict__ srev, size_t lda,
    const __half* __restrict__ Bsrc, size_t ldb, int tid) {
#pragma unroll
    for (int j = 0; j < 4; j++) {        // A: 128 rows x 8 chunks of 8 halves
        int idx = tid + j * NTHREADS;    // 0..1023
        int row = idx >> 3, c8 = (idx & 7) << 3;
        const __half* src = GATHER
            ? Abase + (size_t)srev[row] * lda + c8
            : Abase + (size_t)row * lda + c8;
        cp16(sA + (uint32_t)(row * PA + c8) * 2, src);
    }
#pragma unroll
    for (int j = 0; j < 4; j++) {        // B: 64 k-rows x 16 chunks
        int idx = tid + j * NTHREADS;
        int k = idx >> 4, c8 = (idx & 15) << 3;
        cp16(sB + (uint32_t)(k * PB + c8) * 2, Bsrc + (size_t)k * ldb + c8);
    }
}

// One smem stage: 4 k16 steps x (4 A-ldsm + 2 B-ldsm + 16 HMMA)
// Warp tile 64(M) x 32(N): 4 m-tiles x 4 n-tiles.
__device__ __forceinline__ void compute_stage(
    uint32_t aAddr, uint32_t bAddr,
    int lane, int wm, int wn, float acc[4][4][4]) {
    int g = lane >> 3, tr = lane & 7;
    // A tiles: g0=rows0-7@k0, g1=rows8-15@k0, g2=rows0-7@k8, g3=rows8-15@k8
    uint32_t aLane = aAddr +
        (uint32_t)(((wm * 64 + (g & 1) * 8 + tr) * PA + (g >> 1) * 8) * 2);
    // B tiles (trans): g0=k0-7@n0, g1=k8-15@n0, g2=k0-7@n8, g3=k8-15@n8
    uint32_t bLane = bAddr +
        (uint32_t)((((g & 1) * 8 + tr) * PB + wn * 32 + (g >> 1) * 8) * 2);
#pragma unroll
    for (int k16 = 0; k16 < 4; k16++) {
        uint32_t a[4][4];
#pragma unroll
        for (int m2 = 0; m2 < 4; m2++)
            ldsm_x4(a[m2], aLane + (uint32_t)((m2 * 16 * PA + k16 * 16) * 2));
        uint32_t b[2][4];                // b[nn] = frags for n-tiles 2nn,2nn+1
#pragma unroll
        for (int nn = 0; nn < 2; nn++)
            ldsm_x4_t(b[nn], bLane + (uint32_t)((k16 * 16 * PB + nn * 16) * 2));
#pragma unroll
        for (int m2 = 0; m2 < 4; m2++)
#pragma unroll
            for (int n2 = 0; n2 < 4; n2++)
                mma16n8k16(acc[m2][n2], a[m2], &b[n2 >> 1][(n2 & 1) * 2]);
    }
}

template <bool GATHER>
__device__ __forceinline__ void gemm_mainloop(
    const __half* __restrict__ Abase, const int* __restrict__ srev,
    size_t lda, const __half* __restrict__ Bsrc, size_t ldb,
    uint32_t sA, uint32_t sB,
    int S, int tid, int lane, int wm, int wn, float acc[4][4][4]) {
#pragma unroll
    for (int p = 0; p < STAGES - 1; p++) {
        issue_stage<GATHER>(sA + p * STAGE_B, sB + p * STAGE_B,
                            Abase + p * BKH, srev, lda,
                            Bsrc + (size_t)(p * BKH) * ldb, ldb, tid);
        CP_COMMIT();
    }
    for (int s = 0; s < S; s++) {
        if (s + 1 < S) CP_WAIT(1); else CP_WAIT(0);
        __syncthreads();
        int nx = s + STAGES - 1;
        if (nx < S) {
            int bufn = nx % STAGES;
            issue_stage<GATHER>(sA + bufn * STAGE_B, sB + bufn * STAGE_B,
                                Abase + nx * BKH, srev, lda,
                                Bsrc + (size_t)(nx * BKH) * ldb, ldb, tid);
            CP_COMMIT();
        }
        int buf = s % STAGES;
        compute_stage(sA + buf * STAGE_B, sB + buf * STAGE_B,
                      lane, wm, wn, acc);
    }
}

// GEMM1: h = f16( gelu( gather(xh, rev) @ w1h[e] ) )   [K=1024, 16 stages]
__global__ __launch_bounds__(NTHREADS, 2) void gemm1_mma() {
    extern __shared__ uint32_t smem[];
    int* srev = (int*)((char*)smem + STAGES * STAGE_B);
    uint32_t sbase = (uint32_t)__cvta_generic_to_shared(smem);
    uint32_t sA = sbase, sB = sbase + A_BUF_H * 2;

    int tid = threadIdx.x, lane = tid & 31, wid = tid >> 5;
    int mt = blockIdx.x, ntb = blockIdx.y, e = blockIdx.z;
    const __half* w1e = g_w1h + (size_t)e * D_MODEL * FF_DIM;
    int nb = ntb * BN;
    if (tid < BM) srev[tid] = g_rev[e * CHUNK + mt * BM + tid];
    __syncthreads();

    int wm = wid & 1, wn = wid >> 1;     // 2(m) x 4(n) warps, 64x32 tiles
    float acc[4][4][4];
#pragma unroll
    for (int i = 0; i < 4; i++)
#pragma unroll
        for (int j = 0; j < 4; j++)
#pragma unroll
            for (int c = 0; c < 4; c++) acc[i][j][c] = 0.f;

    gemm_mainloop<true>(g_xh, srev, D_MODEL, w1e + nb, FF_DIM,
                        sA, sB, D_MODEL / BKH, tid, lane, wm, wn, acc);

    // Epilogue: GELU -> g_h (fp16 RN)
    int hrow0 = e * CHUNK + mt * BM;
#pragma unroll
    for (int m2 = 0; m2 < 4; m2++) {
        int r0 = wm * 64 + m2 * 16 + (lane >> 2);
#pragma unroll
        for (int half = 0; half < 2; half++) {
            __half* hr = g_h + (size_t)(hrow0 + r0 + half * 8) * FF_DIM + nb;
#pragma unroll
            for (int n2 = 0; n2 < 4; n2++) {
                int col = wn * 32 + n2 * 8 + 2 * (lane & 3);
                __half2 o = __floats2half2_rn(
                    gelu_exact(acc[m2][n2][half * 2 + 0]),
                    gelu_exact(acc[m2][n2][half * 2 + 1]));
                *(__half2*)(hr + col) = o;
            }
        }
    }
}

// GEMM2: out[token] += (h @ w2h[e]) * sw   (fused scatter, RED no-return)
__global__ __launch_bounds__(NTHREADS, 2) void gemm2_mma(float* __restrict__ out) {
    extern __shared__ uint32_t smem[];
    uint32_t sbase = (uint32_t)__cvta_generic_to_shared(smem);
    uint32_t sA = sbase, sB = sbase + A_BUF_H * 2;

    int tid = threadIdx.x, lane = tid & 31, wid = tid >> 5;
    int mt = blockIdx.x, ntb = blockIdx.y, e = blockIdx.z;
    const __half* w2e = g_w2h + (size_t)e * FF_DIM * D_MODEL;
    const __half* Aep = g_h + (size_t)(e * CHUNK + mt * BM) * FF_DIM;
    int nb = ntb * BN;

    int wm = wid & 1, wn = wid >> 1;
    float acc[4][4][4];
#pragma unroll
    for (int i = 0; i < 4; i++)
#pragma unroll
        for (int j = 0; j < 4; j++)
#pragma unroll
            for (int c = 0; c < 4; c++) acc[i][j][c] = 0.f;

    gemm_mainloop<false>(Aep, nullptr, FF_DIM, w2e + nb, D_MODEL,
                         sA, sB, FF_DIM / BKH, tid, lane, wm, wn, acc);

    // Epilogue: gate-weight scale + scatter-add into out[token].
    // Each token gets exactly 2 adds (a+b commutative -> bit-identical).
    int srow0 = e * CHUNK + mt * BM;
#pragma unroll
    for (int m2 = 0; m2 < 4; m2++) {
        int r0 = wm * 64 + m2 * 16 + (lane >> 2);
#pragma unroll
        for (int half = 0; half < 2; half++) {
            int srow = srow0 + r0 + half * 8;
            float w = g_sw[srow];
            int token = g_rev[srow];
            float* orow = out + (size_t)token * D_MODEL + nb;
#pragma unroll
            for (int n2 = 0; n2 < 4; n2++) {
                int col = wn * 32 + n2 * 8 + 2 * (lane & 3);
                atomicAdd(&orow[col + 0], acc[m2][n2][half * 2 + 0] * w);
                atomicAdd(&orow[col + 1], acc[m2][n2][half * 2 + 1] * w);
            }
        }
    }
}

// ---------------------------------------------------------------------------
extern "C" void kernel_launch(void* const* d_in, const int* in_sizes, int n_in,
                              void* d_out, int out_size) {
    const float* x  = (const float*)d_in[0];   // [4,2048,1024]
    const float* rw = (const float*)d_in[1];   // [8,1024]
    const float* w1 = (const float*)d_in[2];   // [8,1024,4096]
    const float* w2 = (const float*)d_in[3];   // [8,4096,1024]
    float* out = (float*)d_out;                // [4,2048,1024]

    // Idempotent, called every time (no static guards per harness rules)
    cudaFuncSetAttribute(gemm1_mma,
        cudaFuncAttributeMaxDynamicSharedMemorySize, SMEM_BYTES);
    cudaFuncSetAttribute(gemm2_mma,
        cudaFuncAttributeMaxDynamicSharedMemorySize, SMEM_BYTES);

    __half *w1h_p, *w2h_p, *xh_p;
    cudaGetSymbolAddress((void**)&w1h_p, g_w1h);
    cudaGetSymbolAddress((void**)&w2h_p, g_w2h);
    cudaGetSymbolAddress((void**)&xh_p, g_xh);

    // Side streams + events: weight conversions run parallel to router/sort
    // and (for w2) under gemm1. Event edges keep this graph-capturable.
    // All handles are DESTROYED below (after their join) to restore the
    // device-memory baseline the harness checks post-teardown.
    cudaStream_t s1, s2;
    cudaStreamCreateWithFlags(&s1, cudaStreamNonBlocking);
    cudaStreamCreateWithFlags(&s2, cudaStreamNonBlocking);
    cudaEvent_t evFork, evW1, evW2;
    cudaEventCreateWithFlags(&evFork, cudaEventDisableTiming);
    cudaEventCreateWithFlags(&evW1, cudaEventDisableTiming);
    cudaEventCreateWithFlags(&evW2, cudaEventDisableTiming);

    int nw = NE * D_MODEL * FF_DIM / 4;        // 8.39M float4 each
    cudaEventRecord(evFork, 0);
    cudaStreamWaitEvent(s1, evFork, 0);
    cudaStreamWaitEvent(s2, evFork, 0);
    conv_f16_kernel<<<4096, 256, 0, s1>>>((const float4*)w1, (uint2*)w1h_p, nw);
    cudaEventRecord(evW1, s1);
    conv_f16_kernel<<<4096, 256, 0, s2>>>((const float4*)w2, (uint2*)w2h_p, nw);
    cudaEventRecord(evW2, s2);

    // Default stream: zero out, router (fused x->fp16), sort
    int n4 = (N_TOK * D_MODEL) / 4;
    zero_kernel<<<(n4 + 255) / 256, 256>>>((float4*)out, n4);
    router_kernel<<<N_TOK / 8, 256>>>((const float4*)x, (const float4*)rw,
                                      (uint2*)xh_p);
    sort_kernel<<<1, 256>>>();

    cudaStreamWaitEvent(0, evW1, 0);           // join s1: gemm1 needs w1h
    dim3 g1(CHUNK / BM, FF_DIM / BN, NE);      // 16 x 32 x 8
    gemm1_mma<<<g1, NTHREADS, SMEM_BYTES>>>();

    cudaStreamWaitEvent(0, evW2, 0);           // join s2: gemm2 needs w2h
    dim3 g2(CHUNK / BM, D_MODEL / BN, NE);     // 16 x 8 x 8
    gemm2_mma<<<g2, NTHREADS, SMEM_BYTES>>>(out);

    // Both side streams are joined into stream 0 above; safe to release.
    cudaEventDestroy(evFork);
    cudaEventDestroy(evW1);
    cudaEventDestroy(evW2);
    cudaStreamDestroy(s1);
    cudaStreamDestroy(s2);
}